// round 1
// baseline (speedup 1.0000x reference)
#include <cuda_runtime.h>
#include <cstdint>

// Problem constants (fixed by the reference setup)
#define N_SAMPLES 4194304
#define N_RAYS    65536
#define SPT       16      // samples per thread (contiguous span)
#define TPB       256

// ---------------------------------------------------------------------------
// Zero the output (harness poisons d_out to 0xAA before timing).
// ---------------------------------------------------------------------------
__global__ void zero_out_kernel(float4* __restrict__ out4, int n4) {
    int i = blockIdx.x * blockDim.x + threadIdx.x;
    if (i < n4) out4[i] = make_float4(0.f, 0.f, 0.f, 0.f);
}

// ---------------------------------------------------------------------------
// Sorted segment-sum: each thread owns a contiguous span of SPT samples,
// accumulates weighted rgb for runs of equal ray index in registers, and
// atomically flushes only at run boundaries. With mean segment length 64 and
// SPT=16, most threads flush exactly 1-2 times.
// ---------------------------------------------------------------------------
__global__ __launch_bounds__(TPB)
void integrate_color_kernel(const float4* __restrict__ rgb4,   // [N*3/4]
                            const float4* __restrict__ w4,     // [N/4]
                            const int4*   __restrict__ idx4,   // [N/4]
                            float*        __restrict__ out)    // [N_RAYS*3]
{
    const int t = blockIdx.x * blockDim.x + threadIdx.x;

    // ---- front-batched vector loads (max MLP) ----
    int4   iv[SPT / 4];
    float4 wv[SPT / 4];
    float4 cv[(SPT * 3) / 4];

    const long vb = (long)t * (SPT / 4);
    #pragma unroll
    for (int i = 0; i < SPT / 4; ++i) {
        iv[i] = idx4[vb + i];
        wv[i] = w4[vb + i];
    }
    const long cb = (long)t * ((SPT * 3) / 4);
    #pragma unroll
    for (int i = 0; i < (SPT * 3) / 4; ++i) {
        cv[i] = rgb4[cb + i];
    }

    // ---- unpack into flat register arrays (indices constant post-unroll) ----
    int   ridx[SPT];
    float wgt[SPT];
    float col[SPT * 3];
    #pragma unroll
    for (int i = 0; i < SPT / 4; ++i) {
        ridx[4*i + 0] = iv[i].x; ridx[4*i + 1] = iv[i].y;
        ridx[4*i + 2] = iv[i].z; ridx[4*i + 3] = iv[i].w;
        wgt[4*i + 0] = wv[i].x;  wgt[4*i + 1] = wv[i].y;
        wgt[4*i + 2] = wv[i].z;  wgt[4*i + 3] = wv[i].w;
    }
    #pragma unroll
    for (int i = 0; i < (SPT * 3) / 4; ++i) {
        col[4*i + 0] = cv[i].x; col[4*i + 1] = cv[i].y;
        col[4*i + 2] = cv[i].z; col[4*i + 3] = cv[i].w;
    }

    // ---- run-length accumulate + boundary flush ----
    float ax = 0.f, ay = 0.f, az = 0.f;
    int cur = ridx[0];

    #pragma unroll
    for (int i = 0; i < SPT; ++i) {
        const int r = ridx[i];
        if (r != cur) {
            atomicAdd(&out[3 * cur + 0], ax);
            atomicAdd(&out[3 * cur + 1], ay);
            atomicAdd(&out[3 * cur + 2], az);
            cur = r;
            ax = ay = az = 0.f;
        }
        const float w = wgt[i];
        ax = fmaf(w, col[3*i + 0], ax);
        ay = fmaf(w, col[3*i + 1], ay);
        az = fmaf(w, col[3*i + 2], az);
    }
    atomicAdd(&out[3 * cur + 0], ax);
    atomicAdd(&out[3 * cur + 1], ay);
    atomicAdd(&out[3 * cur + 2], az);
}

// ---------------------------------------------------------------------------
// Harness entry. Inputs (metadata order): rgb_samples[f32 N*3],
// weights_samples[f32 N], ray_indices[i32 N], n_rays[i32 scalar].
// Output: f32 [N_RAYS*3].
// ---------------------------------------------------------------------------
extern "C" void kernel_launch(void* const* d_in, const int* in_sizes, int n_in,
                              void* d_out, int out_size)
{
    const float4* rgb4 = (const float4*)d_in[0];
    const float4* w4   = (const float4*)d_in[1];
    const int4*   idx4 = (const int4*)d_in[2];
    float*        out  = (float*)d_out;

    // zero the output: N_RAYS*3 = 196608 floats = 49152 float4
    const int n4 = (N_RAYS * 3) / 4;
    zero_out_kernel<<<(n4 + TPB - 1) / TPB, TPB>>>((float4*)d_out, n4);

    // scatter-accumulate: 4194304 / 16 = 262144 threads
    const int n_threads = N_SAMPLES / SPT;
    integrate_color_kernel<<<n_threads / TPB, TPB>>>(rgb4, w4, idx4, out);
}

// round 3
// speedup vs baseline: 1.0718x; 1.0718x over previous
#include <cuda_runtime.h>
#include <cstdint>

// Problem constants (fixed by the reference setup)
#define N_SAMPLES 4194304
#define N_RAYS    65536
#define SPT       8       // samples per thread (contiguous span)
#define TPB       256

// ---------------------------------------------------------------------------
// Zero the output (harness poisons d_out to 0xAA before timing).
// ---------------------------------------------------------------------------
__global__ void zero_out_kernel(float4* __restrict__ out4, int n4) {
    int i = blockIdx.x * blockDim.x + threadIdx.x;
    if (i < n4) out4[i] = make_float4(0.f, 0.f, 0.f, 0.f);
}

// ---------------------------------------------------------------------------
// Sorted segment-sum: each thread owns a contiguous span of SPT samples,
// accumulates weighted rgb for runs of equal ray index in registers, and
// atomically flushes only at run boundaries. Mean segment length 64 samples
// (= 8 threads at SPT=8), so most threads flush at most twice.
// SPT=8 keeps live registers low enough for 4 blocks/SM (50% occupancy).
// ---------------------------------------------------------------------------
__global__ __launch_bounds__(TPB)
void integrate_color_kernel(const float4* __restrict__ rgb4,   // [N*3/4]
                            const float4* __restrict__ w4,     // [N/4]
                            const int4*   __restrict__ idx4,   // [N/4]
                            float*        __restrict__ out)    // [N_RAYS*3]
{
    const int t = blockIdx.x * blockDim.x + threadIdx.x;

    // ---- front-batched vector loads (max MLP, minimal live range) ----
    int4   iv[SPT / 4];            // 2 x int4
    float4 wv[SPT / 4];            // 2 x float4
    float4 cv[(SPT * 3) / 4];      // 6 x float4

    const long vb = (long)t * (SPT / 4);
    #pragma unroll
    for (int i = 0; i < SPT / 4; ++i) {
        iv[i] = idx4[vb + i];
        wv[i] = w4[vb + i];
    }
    const long cb = (long)t * ((SPT * 3) / 4);
    #pragma unroll
    for (int i = 0; i < (SPT * 3) / 4; ++i) {
        cv[i] = rgb4[cb + i];
    }

    // ---- unpack into flat register arrays (indices constant post-unroll) ----
    int   ridx[SPT];
    float wgt[SPT];
    float col[SPT * 3];
    #pragma unroll
    for (int i = 0; i < SPT / 4; ++i) {
        ridx[4*i + 0] = iv[i].x; ridx[4*i + 1] = iv[i].y;
        ridx[4*i + 2] = iv[i].z; ridx[4*i + 3] = iv[i].w;
        wgt[4*i + 0] = wv[i].x;  wgt[4*i + 1] = wv[i].y;
        wgt[4*i + 2] = wv[i].z;  wgt[4*i + 3] = wv[i].w;
    }
    #pragma unroll
    for (int i = 0; i < (SPT * 3) / 4; ++i) {
        col[4*i + 0] = cv[i].x; col[4*i + 1] = cv[i].y;
        col[4*i + 2] = cv[i].z; col[4*i + 3] = cv[i].w;
    }

    // ---- run-length accumulate + boundary flush ----
    float ax = 0.f, ay = 0.f, az = 0.f;
    int cur = ridx[0];

    #pragma unroll
    for (int i = 0; i < SPT; ++i) {
        const int r = ridx[i];
        if (r != cur) {
            atomicAdd(&out[3 * cur + 0], ax);
            atomicAdd(&out[3 * cur + 1], ay);
            atomicAdd(&out[3 * cur + 2], az);
            cur = r;
            ax = ay = az = 0.f;
        }
        const float w = wgt[i];
        ax = fmaf(w, col[3*i + 0], ax);
        ay = fmaf(w, col[3*i + 1], ay);
        az = fmaf(w, col[3*i + 2], az);
    }
    atomicAdd(&out[3 * cur + 0], ax);
    atomicAdd(&out[3 * cur + 1], ay);
    atomicAdd(&out[3 * cur + 2], az);
}

// ---------------------------------------------------------------------------
// Harness entry. Inputs (metadata order): rgb_samples[f32 N*3],
// weights_samples[f32 N], ray_indices[i32 N], n_rays[i32 scalar].
// Output: f32 [N_RAYS*3].
// ---------------------------------------------------------------------------
extern "C" void kernel_launch(void* const* d_in, const int* in_sizes, int n_in,
                              void* d_out, int out_size)
{
    const float4* rgb4 = (const float4*)d_in[0];
    const float4* w4   = (const float4*)d_in[1];
    const int4*   idx4 = (const int4*)d_in[2];
    float*        out  = (float*)d_out;

    // zero the output: N_RAYS*3 = 196608 floats = 49152 float4
    const int n4 = (N_RAYS * 3) / 4;
    zero_out_kernel<<<(n4 + TPB - 1) / TPB, TPB>>>((float4*)d_out, n4);

    // scatter-accumulate: 4194304 / 8 = 524288 threads
    const int n_threads = N_SAMPLES / SPT;
    integrate_color_kernel<<<n_threads / TPB, TPB>>>(rgb4, w4, idx4, out);
}